// round 6
// baseline (speedup 1.0000x reference)
#include <cuda_runtime.h>
#include <cuda_bf16.h>
#include <math.h>

// ---------------------------------------------------------------------------
// ConvNet: conv(3->16,5x5) -> hermite -> pool2 -> conv(16->16,5x5) -> hermite
//          -> pool2 -> FC(2704->10).  B=512, input 3x64x64.
// Round 5: R4 inner loop (vector LDS) + occupancy fix: 768-thread CTAs with
// 4 thread-groups x 4 output channels each -> acc tile 16 regs, 48 warps/SM.
// ---------------------------------------------------------------------------

#define B_IMG 512

__device__ float g_pool1[B_IMG * 16 * 30 * 30];   // after conv1+herm+pool
__device__ float g_pool2[B_IMG * 16 * 13 * 13];   // after conv2+herm+pool

__device__ __forceinline__ float herm4(float x, float a0, float a1, float a2,
                                       float a3, float a4) {
    return fmaf(fmaf(fmaf(fmaf(a4, x, a3), x, a2), x, a1), x, a0);
}

// ---------------------------------------------------------------------------
// Kernel 1: conv1 + bias + hermite + maxpool2
// Grid: 512 images * 5 row-bands, 768 threads = 4 groups x 192 (180 active).
// Group g computes output channels [4g, 4g+4).
// Smem: padded weights 16*3*5*8 = 1920, input 3*16*64 = 3072, bias 16 (~20KB).
// ---------------------------------------------------------------------------
__global__ void __launch_bounds__(768, 2)
conv1_fused_kernel(const float* __restrict__ x,
                   const float* __restrict__ coef,
                   const float* __restrict__ w,
                   const float* __restrict__ bias) {
    extern __shared__ float smem[];
    float* s_w  = smem;                           // 1920 (16B aligned)
    float* s_in = smem + 1920;                    // 3072
    float* s_b  = s_in + 3 * 16 * 64;             // 16

    const int img  = blockIdx.x / 5;
    const int band = blockIdx.x % 5;
    const int tid  = threadIdx.x;                 // 768

    const float* xim = x + (size_t)img * 3 * 64 * 64;
    const int row0 = band * 12;
    for (int i = tid; i < 3 * 16 * 64; i += 768) {
        int c   = i >> 10;
        int rem = i & 1023;
        s_in[i] = xim[c * 4096 + row0 * 64 + rem];
    }
    // pad weights: dst[((co*3+cin)*5+ky)*8 + kx] = w[co*75+cin*25+ky*5+kx]
    for (int i = tid; i < 1200; i += 768) {
        int co  = i / 75;
        int r   = i % 75;
        int cin = r / 25;
        int r2  = r % 25;
        int ky  = r2 / 5;
        int kx  = r2 % 5;
        s_w[((co * 3 + cin) * 5 + ky) * 8 + kx] = w[i];
    }
    if (tid < 16) s_b[tid] = bias[tid];
    __syncthreads();

    const int g = tid / 192;                      // group: co [4g, 4g+4)
    const int t = tid % 192;

    if (t < 180) {
        const int pyl = t / 30;
        const int px  = t % 30;
        const int oy  = 2 * pyl;
        const int ox  = 2 * px;
        const int co0 = g * 4;

        float acc[4][4];
        #pragma unroll
        for (int co = 0; co < 4; co++) {
            float bv = s_b[co0 + co];
            acc[co][0] = bv; acc[co][1] = bv; acc[co][2] = bv; acc[co][3] = bv;
        }

        #pragma unroll 1
        for (int cin = 0; cin < 3; cin++) {
            const float* rowp = s_in + cin * 1024 + oy * 64 + ox;
            float va[6], vb[6];
            {
                const float2* q = (const float2*)rowp;
                float2 t0 = q[0], t1 = q[1], t2 = q[2];
                va[0] = t0.x; va[1] = t0.y; va[2] = t1.x;
                va[3] = t1.y; va[4] = t2.x; va[5] = t2.y;
            }
            rowp += 64;
            {
                const float2* q = (const float2*)rowp;
                float2 t0 = q[0], t1 = q[1], t2 = q[2];
                vb[0] = t0.x; vb[1] = t0.y; vb[2] = t1.x;
                vb[3] = t1.y; vb[4] = t2.x; vb[5] = t2.y;
            }

            const float* wbase = s_w + (co0 * 3 + cin) * 40;   // co stride 120
            #pragma unroll
            for (int ky = 0; ky < 5; ky++) {
                if (ky) {
                    #pragma unroll
                    for (int k = 0; k < 6; k++) va[k] = vb[k];
                    rowp += 64;
                    const float2* q = (const float2*)rowp;
                    float2 t0 = q[0], t1 = q[1], t2 = q[2];
                    vb[0] = t0.x; vb[1] = t0.y; vb[2] = t1.x;
                    vb[3] = t1.y; vb[4] = t2.x; vb[5] = t2.y;
                }
                #pragma unroll
                for (int co = 0; co < 4; co++) {
                    const float* wrow = wbase + co * 120 + ky * 8;
                    float4 w03 = *(const float4*)wrow;
                    float  w4  = wrow[4];
                    acc[co][0] = fmaf(va[0], w03.x, acc[co][0]);
                    acc[co][1] = fmaf(va[1], w03.x, acc[co][1]);
                    acc[co][2] = fmaf(vb[0], w03.x, acc[co][2]);
                    acc[co][3] = fmaf(vb[1], w03.x, acc[co][3]);
                    acc[co][0] = fmaf(va[1], w03.y, acc[co][0]);
                    acc[co][1] = fmaf(va[2], w03.y, acc[co][1]);
                    acc[co][2] = fmaf(vb[1], w03.y, acc[co][2]);
                    acc[co][3] = fmaf(vb[2], w03.y, acc[co][3]);
                    acc[co][0] = fmaf(va[2], w03.z, acc[co][0]);
                    acc[co][1] = fmaf(va[3], w03.z, acc[co][1]);
                    acc[co][2] = fmaf(vb[2], w03.z, acc[co][2]);
                    acc[co][3] = fmaf(vb[3], w03.z, acc[co][3]);
                    acc[co][0] = fmaf(va[3], w03.w, acc[co][0]);
                    acc[co][1] = fmaf(va[4], w03.w, acc[co][1]);
                    acc[co][2] = fmaf(vb[3], w03.w, acc[co][2]);
                    acc[co][3] = fmaf(vb[4], w03.w, acc[co][3]);
                    acc[co][0] = fmaf(va[4], w4, acc[co][0]);
                    acc[co][1] = fmaf(va[5], w4, acc[co][1]);
                    acc[co][2] = fmaf(vb[4], w4, acc[co][2]);
                    acc[co][3] = fmaf(vb[5], w4, acc[co][3]);
                }
            }
        }

        const float c0 = __ldg(coef + 0), c1 = __ldg(coef + 1),
                    c2 = __ldg(coef + 2), c3 = __ldg(coef + 3),
                    c4 = __ldg(coef + 4);
        const float a0 = c0 - 2.0f * c2 + 12.0f * c4;
        const float a1 = 2.0f * c1 - 12.0f * c3;
        const float a2 = 4.0f * c2 - 48.0f * c4;
        const float a3 = 8.0f * c3;
        const float a4 = 16.0f * c4;

        const int py = band * 6 + pyl;
        #pragma unroll
        for (int co = 0; co < 4; co++) {
            float h0 = herm4(acc[co][0], a0, a1, a2, a3, a4);
            float h1 = herm4(acc[co][1], a0, a1, a2, a3, a4);
            float h2 = herm4(acc[co][2], a0, a1, a2, a3, a4);
            float h3 = herm4(acc[co][3], a0, a1, a2, a3, a4);
            float m = fmaxf(fmaxf(h0, h1), fmaxf(h2, h3));
            g_pool1[((img * 16 + co0 + co) * 30 + py) * 30 + px] = m;
        }
    }
}

// ---------------------------------------------------------------------------
// Kernel 2: conv2 + bias + hermite + maxpool2
// Grid: 512 blocks (one image), 768 threads = 4 groups x 192 (169 active).
// Group g computes output channels [4g, 4g+4).
// Smem: padded weights 16*16*5*8 = 10240 (40KB) + input 14400 (57.6KB) + bias
//       = ~98.6 KB -> 2 CTAs/SM, 48 warps.
// ---------------------------------------------------------------------------
__global__ void __launch_bounds__(768, 2)
conv2_fused_kernel(const float* __restrict__ coef,
                   const float* __restrict__ w,
                   const float* __restrict__ bias) {
    extern __shared__ float smem[];
    float* s_w  = smem;                           // 10240
    float* s_in = smem + 10240;                   // 14400
    float* s_b  = s_in + 14400;                   // 16

    const int img = blockIdx.x;
    const int tid = threadIdx.x;                  // 768

    const float* xim = g_pool1 + (size_t)img * 14400;
    for (int i = tid; i < 14400; i += 768) s_in[i] = xim[i];
    // pad: dst[((co*16+cin)*5+ky)*8 + kx] = w[co*400+cin*25+ky*5+kx]
    for (int i = tid; i < 6400; i += 768) {
        int co  = i / 400;
        int r   = i % 400;
        int cin = r / 25;
        int r2  = r % 25;
        int ky  = r2 / 5;
        int kx  = r2 % 5;
        s_w[((co * 16 + cin) * 5 + ky) * 8 + kx] = w[i];
    }
    if (tid < 16) s_b[tid] = bias[tid];
    __syncthreads();

    const int g = tid / 192;                      // group: co [4g, 4g+4)
    const int t = tid % 192;

    if (t < 169) {
        const int py = t / 13;
        const int px = t % 13;
        const int oy = 2 * py;
        const int ox = 2 * px;
        const int co0 = g * 4;

        float acc[4][4];
        #pragma unroll
        for (int co = 0; co < 4; co++) {
            float bv = s_b[co0 + co];
            acc[co][0] = bv; acc[co][1] = bv; acc[co][2] = bv; acc[co][3] = bv;
        }

        #pragma unroll 1
        for (int cin = 0; cin < 16; cin++) {
            const float* rowp = s_in + cin * 900 + oy * 30 + ox;
            float va[6], vb[6];
            {
                const float2* q = (const float2*)rowp;
                float2 t0 = q[0], t1 = q[1], t2 = q[2];
                va[0] = t0.x; va[1] = t0.y; va[2] = t1.x;
                va[3] = t1.y; va[4] = t2.x; va[5] = t2.y;
            }
            rowp += 30;
            {
                const float2* q = (const float2*)rowp;
                float2 t0 = q[0], t1 = q[1], t2 = q[2];
                vb[0] = t0.x; vb[1] = t0.y; vb[2] = t1.x;
                vb[3] = t1.y; vb[4] = t2.x; vb[5] = t2.y;
            }

            const float* wbase = s_w + (co0 * 16 + cin) * 40;   // co stride 640
            #pragma unroll
            for (int ky = 0; ky < 5; ky++) {
                if (ky) {
                    #pragma unroll
                    for (int k = 0; k < 6; k++) va[k] = vb[k];
                    rowp += 30;
                    const float2* q = (const float2*)rowp;
                    float2 t0 = q[0], t1 = q[1], t2 = q[2];
                    vb[0] = t0.x; vb[1] = t0.y; vb[2] = t1.x;
                    vb[3] = t1.y; vb[4] = t2.x; vb[5] = t2.y;
                }
                #pragma unroll
                for (int co = 0; co < 4; co++) {
                    const float* wrow = wbase + co * 640 + ky * 8;
                    float4 w03 = *(const float4*)wrow;
                    float  w4  = wrow[4];
                    acc[co][0] = fmaf(va[0], w03.x, acc[co][0]);
                    acc[co][1] = fmaf(va[1], w03.x, acc[co][1]);
                    acc[co][2] = fmaf(vb[0], w03.x, acc[co][2]);
                    acc[co][3] = fmaf(vb[1], w03.x, acc[co][3]);
                    acc[co][0] = fmaf(va[1], w03.y, acc[co][0]);
                    acc[co][1] = fmaf(va[2], w03.y, acc[co][1]);
                    acc[co][2] = fmaf(vb[1], w03.y, acc[co][2]);
                    acc[co][3] = fmaf(vb[2], w03.y, acc[co][3]);
                    acc[co][0] = fmaf(va[2], w03.z, acc[co][0]);
                    acc[co][1] = fmaf(va[3], w03.z, acc[co][1]);
                    acc[co][2] = fmaf(vb[2], w03.z, acc[co][2]);
                    acc[co][3] = fmaf(vb[3], w03.z, acc[co][3]);
                    acc[co][0] = fmaf(va[3], w03.w, acc[co][0]);
                    acc[co][1] = fmaf(va[4], w03.w, acc[co][1]);
                    acc[co][2] = fmaf(vb[3], w03.w, acc[co][2]);
                    acc[co][3] = fmaf(vb[4], w03.w, acc[co][3]);
                    acc[co][0] = fmaf(va[4], w4, acc[co][0]);
                    acc[co][1] = fmaf(va[5], w4, acc[co][1]);
                    acc[co][2] = fmaf(vb[4], w4, acc[co][2]);
                    acc[co][3] = fmaf(vb[5], w4, acc[co][3]);
                }
            }
        }

        const float c0 = __ldg(coef + 0), c1 = __ldg(coef + 1),
                    c2 = __ldg(coef + 2), c3 = __ldg(coef + 3),
                    c4 = __ldg(coef + 4);
        const float a0 = c0 - 2.0f * c2 + 12.0f * c4;
        const float a1 = 2.0f * c1 - 12.0f * c3;
        const float a2 = 4.0f * c2 - 48.0f * c4;
        const float a3 = 8.0f * c3;
        const float a4 = 16.0f * c4;

        #pragma unroll
        for (int co = 0; co < 4; co++) {
            float h0 = herm4(acc[co][0], a0, a1, a2, a3, a4);
            float h1 = herm4(acc[co][1], a0, a1, a2, a3, a4);
            float h2 = herm4(acc[co][2], a0, a1, a2, a3, a4);
            float h3 = herm4(acc[co][3], a0, a1, a2, a3, a4);
            float m = fmaxf(fmaxf(h0, h1), fmaxf(h2, h3));
            g_pool2[((img * 16 + co0 + co) * 13 + py) * 13 + px] = m;
        }
    }
}

// ---------------------------------------------------------------------------
// Kernel 3: FC [512,2704] @ [2704,10]^T + bias
// ---------------------------------------------------------------------------
__global__ void __launch_bounds__(128)
fc_kernel(const float* __restrict__ w,
          const float* __restrict__ bias,
          float* __restrict__ out) {
    const int img = blockIdx.x;
    const int tid = threadIdx.x;   // 128

    const float* xv = g_pool2 + (size_t)img * 2704;
    float p[10];
    #pragma unroll
    for (int o = 0; o < 10; o++) p[o] = 0.0f;

    for (int k = tid; k < 2704; k += 128) {
        float v = xv[k];
        #pragma unroll
        for (int o = 0; o < 10; o++) p[o] = fmaf(v, w[o * 2704 + k], p[o]);
    }

    __shared__ float red[4][10];
    const int lane = tid & 31, wrp = tid >> 5;
    #pragma unroll
    for (int o = 0; o < 10; o++) {
        float v = p[o];
        #pragma unroll
        for (int s = 16; s > 0; s >>= 1)
            v += __shfl_down_sync(0xffffffffu, v, s);
        if (lane == 0) red[wrp][o] = v;
    }
    __syncthreads();
    if (tid < 10)
        out[img * 10 + tid] =
            red[0][tid] + red[1][tid] + red[2][tid] + red[3][tid] + bias[tid];
}

// ---------------------------------------------------------------------------
extern "C" void kernel_launch(void* const* d_in, const int* in_sizes, int n_in,
                              void* d_out, int out_size) {
    const float* x       = (const float*)d_in[0];
    const float* coef    = (const float*)d_in[1];
    const float* conv1_w = (const float*)d_in[2];
    const float* conv1_b = (const float*)d_in[3];
    const float* conv2_w = (const float*)d_in[4];
    const float* conv2_b = (const float*)d_in[5];
    const float* fc1_w   = (const float*)d_in[6];
    const float* fc1_b   = (const float*)d_in[7];
    float* out = (float*)d_out;

    const int smem1 = (1920 + 3 * 16 * 64 + 16) * sizeof(float);   // ~20 KB
    const int smem2 = (10240 + 14400 + 16) * sizeof(float);        // ~98.6 KB

    cudaFuncSetAttribute(conv2_fused_kernel,
                         cudaFuncAttributeMaxDynamicSharedMemorySize, smem2);

    conv1_fused_kernel<<<B_IMG * 5, 768, smem1>>>(x, coef, conv1_w, conv1_b);
    conv2_fused_kernel<<<B_IMG, 768, smem2>>>(coef, conv2_w, conv2_b);
    fc_kernel<<<B_IMG, 128>>>(fc1_w, fc1_b, out);
}

// round 7
// speedup vs baseline: 1.0032x; 1.0032x over previous
#include <cuda_runtime.h>
#include <cuda_bf16.h>
#include <math.h>

// ---------------------------------------------------------------------------
// ConvNet: conv(3->16,5x5) -> hermite -> pool2 -> conv(16->16,5x5) -> hermite
//          -> pool2 -> FC(2704->10).  B=512, input 3x64x64.
// Round 5: R4 inner loop (vector LDS) + occupancy fix: 768-thread CTAs with
// 4 thread-groups x 4 output channels each -> acc tile 16 regs, 48 warps/SM.
// ---------------------------------------------------------------------------

#define B_IMG 512

__device__ float g_pool1[B_IMG * 16 * 30 * 30];   // after conv1+herm+pool
__device__ float g_pool2[B_IMG * 16 * 13 * 13];   // after conv2+herm+pool

__device__ __forceinline__ float herm4(float x, float a0, float a1, float a2,
                                       float a3, float a4) {
    return fmaf(fmaf(fmaf(fmaf(a4, x, a3), x, a2), x, a1), x, a0);
}

// ---------------------------------------------------------------------------
// Kernel 1: conv1 + bias + hermite + maxpool2
// Grid: 512 images * 5 row-bands, 768 threads = 4 groups x 192 (180 active).
// Group g computes output channels [4g, 4g+4).
// Smem: padded weights 16*3*5*8 = 1920, input 3*16*64 = 3072, bias 16 (~20KB).
// ---------------------------------------------------------------------------
__global__ void __launch_bounds__(768, 2)
conv1_fused_kernel(const float* __restrict__ x,
                   const float* __restrict__ coef,
                   const float* __restrict__ w,
                   const float* __restrict__ bias) {
    extern __shared__ float smem[];
    float* s_w  = smem;                           // 1920 (16B aligned)
    float* s_in = smem + 1920;                    // 3072
    float* s_b  = s_in + 3 * 16 * 64;             // 16

    const int img  = blockIdx.x / 5;
    const int band = blockIdx.x % 5;
    const int tid  = threadIdx.x;                 // 768

    const float* xim = x + (size_t)img * 3 * 64 * 64;
    const int row0 = band * 12;
    for (int i = tid; i < 3 * 16 * 64; i += 768) {
        int c   = i >> 10;
        int rem = i & 1023;
        s_in[i] = xim[c * 4096 + row0 * 64 + rem];
    }
    // pad weights: dst[((co*3+cin)*5+ky)*8 + kx] = w[co*75+cin*25+ky*5+kx]
    for (int i = tid; i < 1200; i += 768) {
        int co  = i / 75;
        int r   = i % 75;
        int cin = r / 25;
        int r2  = r % 25;
        int ky  = r2 / 5;
        int kx  = r2 % 5;
        s_w[((co * 3 + cin) * 5 + ky) * 8 + kx] = w[i];
    }
    if (tid < 16) s_b[tid] = bias[tid];
    __syncthreads();

    const int g = tid / 192;                      // group: co [4g, 4g+4)
    const int t = tid % 192;

    if (t < 180) {
        const int pyl = t / 30;
        const int px  = t % 30;
        const int oy  = 2 * pyl;
        const int ox  = 2 * px;
        const int co0 = g * 4;

        float acc[4][4];
        #pragma unroll
        for (int co = 0; co < 4; co++) {
            float bv = s_b[co0 + co];
            acc[co][0] = bv; acc[co][1] = bv; acc[co][2] = bv; acc[co][3] = bv;
        }

        #pragma unroll 1
        for (int cin = 0; cin < 3; cin++) {
            const float* rowp = s_in + cin * 1024 + oy * 64 + ox;
            float va[6], vb[6];
            {
                const float2* q = (const float2*)rowp;
                float2 t0 = q[0], t1 = q[1], t2 = q[2];
                va[0] = t0.x; va[1] = t0.y; va[2] = t1.x;
                va[3] = t1.y; va[4] = t2.x; va[5] = t2.y;
            }
            rowp += 64;
            {
                const float2* q = (const float2*)rowp;
                float2 t0 = q[0], t1 = q[1], t2 = q[2];
                vb[0] = t0.x; vb[1] = t0.y; vb[2] = t1.x;
                vb[3] = t1.y; vb[4] = t2.x; vb[5] = t2.y;
            }

            const float* wbase = s_w + (co0 * 3 + cin) * 40;   // co stride 120
            #pragma unroll
            for (int ky = 0; ky < 5; ky++) {
                if (ky) {
                    #pragma unroll
                    for (int k = 0; k < 6; k++) va[k] = vb[k];
                    rowp += 64;
                    const float2* q = (const float2*)rowp;
                    float2 t0 = q[0], t1 = q[1], t2 = q[2];
                    vb[0] = t0.x; vb[1] = t0.y; vb[2] = t1.x;
                    vb[3] = t1.y; vb[4] = t2.x; vb[5] = t2.y;
                }
                #pragma unroll
                for (int co = 0; co < 4; co++) {
                    const float* wrow = wbase + co * 120 + ky * 8;
                    float4 w03 = *(const float4*)wrow;
                    float  w4  = wrow[4];
                    acc[co][0] = fmaf(va[0], w03.x, acc[co][0]);
                    acc[co][1] = fmaf(va[1], w03.x, acc[co][1]);
                    acc[co][2] = fmaf(vb[0], w03.x, acc[co][2]);
                    acc[co][3] = fmaf(vb[1], w03.x, acc[co][3]);
                    acc[co][0] = fmaf(va[1], w03.y, acc[co][0]);
                    acc[co][1] = fmaf(va[2], w03.y, acc[co][1]);
                    acc[co][2] = fmaf(vb[1], w03.y, acc[co][2]);
                    acc[co][3] = fmaf(vb[2], w03.y, acc[co][3]);
                    acc[co][0] = fmaf(va[2], w03.z, acc[co][0]);
                    acc[co][1] = fmaf(va[3], w03.z, acc[co][1]);
                    acc[co][2] = fmaf(vb[2], w03.z, acc[co][2]);
                    acc[co][3] = fmaf(vb[3], w03.z, acc[co][3]);
                    acc[co][0] = fmaf(va[3], w03.w, acc[co][0]);
                    acc[co][1] = fmaf(va[4], w03.w, acc[co][1]);
                    acc[co][2] = fmaf(vb[3], w03.w, acc[co][2]);
                    acc[co][3] = fmaf(vb[4], w03.w, acc[co][3]);
                    acc[co][0] = fmaf(va[4], w4, acc[co][0]);
                    acc[co][1] = fmaf(va[5], w4, acc[co][1]);
                    acc[co][2] = fmaf(vb[4], w4, acc[co][2]);
                    acc[co][3] = fmaf(vb[5], w4, acc[co][3]);
                }
            }
        }

        const float c0 = __ldg(coef + 0), c1 = __ldg(coef + 1),
                    c2 = __ldg(coef + 2), c3 = __ldg(coef + 3),
                    c4 = __ldg(coef + 4);
        const float a0 = c0 - 2.0f * c2 + 12.0f * c4;
        const float a1 = 2.0f * c1 - 12.0f * c3;
        const float a2 = 4.0f * c2 - 48.0f * c4;
        const float a3 = 8.0f * c3;
        const float a4 = 16.0f * c4;

        const int py = band * 6 + pyl;
        #pragma unroll
        for (int co = 0; co < 4; co++) {
            float h0 = herm4(acc[co][0], a0, a1, a2, a3, a4);
            float h1 = herm4(acc[co][1], a0, a1, a2, a3, a4);
            float h2 = herm4(acc[co][2], a0, a1, a2, a3, a4);
            float h3 = herm4(acc[co][3], a0, a1, a2, a3, a4);
            float m = fmaxf(fmaxf(h0, h1), fmaxf(h2, h3));
            g_pool1[((img * 16 + co0 + co) * 30 + py) * 30 + px] = m;
        }
    }
}

// ---------------------------------------------------------------------------
// Kernel 2: conv2 + bias + hermite + maxpool2
// Grid: 512 blocks (one image), 768 threads = 4 groups x 192 (169 active).
// Group g computes output channels [4g, 4g+4).
// Smem: padded weights 16*16*5*8 = 10240 (40KB) + input 14400 (57.6KB) + bias
//       = ~98.6 KB -> 2 CTAs/SM, 48 warps.
// ---------------------------------------------------------------------------
__global__ void __launch_bounds__(768, 2)
conv2_fused_kernel(const float* __restrict__ coef,
                   const float* __restrict__ w,
                   const float* __restrict__ bias) {
    extern __shared__ float smem[];
    float* s_w  = smem;                           // 10240
    float* s_in = smem + 10240;                   // 14400
    float* s_b  = s_in + 14400;                   // 16

    const int img = blockIdx.x;
    const int tid = threadIdx.x;                  // 768

    const float* xim = g_pool1 + (size_t)img * 14400;
    for (int i = tid; i < 14400; i += 768) s_in[i] = xim[i];
    // pad: dst[((co*16+cin)*5+ky)*8 + kx] = w[co*400+cin*25+ky*5+kx]
    for (int i = tid; i < 6400; i += 768) {
        int co  = i / 400;
        int r   = i % 400;
        int cin = r / 25;
        int r2  = r % 25;
        int ky  = r2 / 5;
        int kx  = r2 % 5;
        s_w[((co * 16 + cin) * 5 + ky) * 8 + kx] = w[i];
    }
    if (tid < 16) s_b[tid] = bias[tid];
    __syncthreads();

    const int g = tid / 192;                      // group: co [4g, 4g+4)
    const int t = tid % 192;

    if (t < 169) {
        const int py = t / 13;
        const int px = t % 13;
        const int oy = 2 * py;
        const int ox = 2 * px;
        const int co0 = g * 4;

        float acc[4][4];
        #pragma unroll
        for (int co = 0; co < 4; co++) {
            float bv = s_b[co0 + co];
            acc[co][0] = bv; acc[co][1] = bv; acc[co][2] = bv; acc[co][3] = bv;
        }

        #pragma unroll 1
        for (int cin = 0; cin < 16; cin++) {
            const float* rowp = s_in + cin * 900 + oy * 30 + ox;
            float va[6], vb[6];
            {
                const float2* q = (const float2*)rowp;
                float2 t0 = q[0], t1 = q[1], t2 = q[2];
                va[0] = t0.x; va[1] = t0.y; va[2] = t1.x;
                va[3] = t1.y; va[4] = t2.x; va[5] = t2.y;
            }
            rowp += 30;
            {
                const float2* q = (const float2*)rowp;
                float2 t0 = q[0], t1 = q[1], t2 = q[2];
                vb[0] = t0.x; vb[1] = t0.y; vb[2] = t1.x;
                vb[3] = t1.y; vb[4] = t2.x; vb[5] = t2.y;
            }

            const float* wbase = s_w + (co0 * 16 + cin) * 40;   // co stride 640
            #pragma unroll
            for (int ky = 0; ky < 5; ky++) {
                if (ky) {
                    #pragma unroll
                    for (int k = 0; k < 6; k++) va[k] = vb[k];
                    rowp += 30;
                    const float2* q = (const float2*)rowp;
                    float2 t0 = q[0], t1 = q[1], t2 = q[2];
                    vb[0] = t0.x; vb[1] = t0.y; vb[2] = t1.x;
                    vb[3] = t1.y; vb[4] = t2.x; vb[5] = t2.y;
                }
                #pragma unroll
                for (int co = 0; co < 4; co++) {
                    const float* wrow = wbase + co * 640 + ky * 8;
                    float4 w03 = *(const float4*)wrow;
                    float  w4  = wrow[4];
                    acc[co][0] = fmaf(va[0], w03.x, acc[co][0]);
                    acc[co][1] = fmaf(va[1], w03.x, acc[co][1]);
                    acc[co][2] = fmaf(vb[0], w03.x, acc[co][2]);
                    acc[co][3] = fmaf(vb[1], w03.x, acc[co][3]);
                    acc[co][0] = fmaf(va[1], w03.y, acc[co][0]);
                    acc[co][1] = fmaf(va[2], w03.y, acc[co][1]);
                    acc[co][2] = fmaf(vb[1], w03.y, acc[co][2]);
                    acc[co][3] = fmaf(vb[2], w03.y, acc[co][3]);
                    acc[co][0] = fmaf(va[2], w03.z, acc[co][0]);
                    acc[co][1] = fmaf(va[3], w03.z, acc[co][1]);
                    acc[co][2] = fmaf(vb[2], w03.z, acc[co][2]);
                    acc[co][3] = fmaf(vb[3], w03.z, acc[co][3]);
                    acc[co][0] = fmaf(va[3], w03.w, acc[co][0]);
                    acc[co][1] = fmaf(va[4], w03.w, acc[co][1]);
                    acc[co][2] = fmaf(vb[3], w03.w, acc[co][2]);
                    acc[co][3] = fmaf(vb[4], w03.w, acc[co][3]);
                    acc[co][0] = fmaf(va[4], w4, acc[co][0]);
                    acc[co][1] = fmaf(va[5], w4, acc[co][1]);
                    acc[co][2] = fmaf(vb[4], w4, acc[co][2]);
                    acc[co][3] = fmaf(vb[5], w4, acc[co][3]);
                }
            }
        }

        const float c0 = __ldg(coef + 0), c1 = __ldg(coef + 1),
                    c2 = __ldg(coef + 2), c3 = __ldg(coef + 3),
                    c4 = __ldg(coef + 4);
        const float a0 = c0 - 2.0f * c2 + 12.0f * c4;
        const float a1 = 2.0f * c1 - 12.0f * c3;
        const float a2 = 4.0f * c2 - 48.0f * c4;
        const float a3 = 8.0f * c3;
        const float a4 = 16.0f * c4;

        #pragma unroll
        for (int co = 0; co < 4; co++) {
            float h0 = herm4(acc[co][0], a0, a1, a2, a3, a4);
            float h1 = herm4(acc[co][1], a0, a1, a2, a3, a4);
            float h2 = herm4(acc[co][2], a0, a1, a2, a3, a4);
            float h3 = herm4(acc[co][3], a0, a1, a2, a3, a4);
            float m = fmaxf(fmaxf(h0, h1), fmaxf(h2, h3));
            g_pool2[((img * 16 + co0 + co) * 13 + py) * 13 + px] = m;
        }
    }
}

// ---------------------------------------------------------------------------
// Kernel 3: FC [512,2704] @ [2704,10]^T + bias
// ---------------------------------------------------------------------------
__global__ void __launch_bounds__(128)
fc_kernel(const float* __restrict__ w,
          const float* __restrict__ bias,
          float* __restrict__ out) {
    const int img = blockIdx.x;
    const int tid = threadIdx.x;   // 128

    const float* xv = g_pool2 + (size_t)img * 2704;
    float p[10];
    #pragma unroll
    for (int o = 0; o < 10; o++) p[o] = 0.0f;

    for (int k = tid; k < 2704; k += 128) {
        float v = xv[k];
        #pragma unroll
        for (int o = 0; o < 10; o++) p[o] = fmaf(v, w[o * 2704 + k], p[o]);
    }

    __shared__ float red[4][10];
    const int lane = tid & 31, wrp = tid >> 5;
    #pragma unroll
    for (int o = 0; o < 10; o++) {
        float v = p[o];
        #pragma unroll
        for (int s = 16; s > 0; s >>= 1)
            v += __shfl_down_sync(0xffffffffu, v, s);
        if (lane == 0) red[wrp][o] = v;
    }
    __syncthreads();
    if (tid < 10)
        out[img * 10 + tid] =
            red[0][tid] + red[1][tid] + red[2][tid] + red[3][tid] + bias[tid];
}

// ---------------------------------------------------------------------------
extern "C" void kernel_launch(void* const* d_in, const int* in_sizes, int n_in,
                              void* d_out, int out_size) {
    const float* x       = (const float*)d_in[0];
    const float* coef    = (const float*)d_in[1];
    const float* conv1_w = (const float*)d_in[2];
    const float* conv1_b = (const float*)d_in[3];
    const float* conv2_w = (const float*)d_in[4];
    const float* conv2_b = (const float*)d_in[5];
    const float* fc1_w   = (const float*)d_in[6];
    const float* fc1_b   = (const float*)d_in[7];
    float* out = (float*)d_out;

    const int smem1 = (1920 + 3 * 16 * 64 + 16) * sizeof(float);   // ~20 KB
    const int smem2 = (10240 + 14400 + 16) * sizeof(float);        // ~98.6 KB

    cudaFuncSetAttribute(conv2_fused_kernel,
                         cudaFuncAttributeMaxDynamicSharedMemorySize, smem2);

    conv1_fused_kernel<<<B_IMG * 5, 768, smem1>>>(x, coef, conv1_w, conv1_b);
    conv2_fused_kernel<<<B_IMG, 768, smem2>>>(coef, conv2_w, conv2_b);
    fc_kernel<<<B_IMG, 128>>>(fc1_w, fc1_b, out);
}